// round 6
// baseline (speedup 1.0000x reference)
#include <cuda_runtime.h>
#include <math.h>

#define EMB    1024
#define NDEC   2048     // WIDTH*MODES*2
#define WIDTH  64
#define MODES  16
#define NH     128      // fc1 hidden
#define MAXB   64
#define KC     16       // K-split chunks in stage A
#define KCHUNK 64       // EMB / KC
#define OT     256      // output-column tile in stage A
#define BH     32       // batches per stage-A block (2-way batch split)
#define NKK    31       // 1 DC + 15 cos + 15 sin
#define TT     64       // t-tile per block in stage C
#define TW     16       // t per warp in stage C
#define NM     15       // MODES-1

typedef unsigned long long u64;

// Scratch (static device globals; no allocation)
__device__ float g_hpart[KC][MAXB * NDEC];   // 8 MB
__device__ float g_coef[MAXB * NKK * NH];    // ~1 MB

// ---- packed f32x2 helpers (sm_100+) --------------------------------------
__device__ __forceinline__ u64 pk2(float lo, float hi) {
    u64 r; asm("mov.b64 %0, {%1, %2};" : "=l"(r) : "f"(lo), "f"(hi)); return r;
}
__device__ __forceinline__ void upk2(u64 v, float& lo, float& hi) {
    asm("mov.b64 {%0, %1}, %2;" : "=f"(lo), "=f"(hi) : "l"(v));
}
__device__ __forceinline__ u64 ffma2(u64 a, u64 b, u64 c) {
    u64 d; asm("fma.rn.f32x2 %0, %1, %2, %3;" : "=l"(d) : "l"(a), "l"(b), "l"(c)); return d;
}
__device__ __forceinline__ u64 fadd2(u64 a, u64 b) {
    u64 d; asm("add.rn.f32x2 %0, %1, %2;" : "=l"(d) : "l"(a), "l"(b)); return d;
}
__device__ __forceinline__ u64 fsub2(u64 a, u64 b) {
    u64 d; asm("sub.rn.f32x2 %0, %1, %2;" : "=l"(d) : "l"(a), "l"(b)); return d;
}
__device__ __forceinline__ u64 fmul2(u64 a, u64 b) {
    u64 d; asm("mul.rn.f32x2 %0, %1, %2;" : "=l"(d) : "l"(a), "l"(b)); return d;
}

// packed exact-enough gelu: Taylor erf for small args (always the real case
// here; |pre| ~ 1e-2), scalar erff fallback otherwise.
__device__ __forceinline__ u64 gelu2(u64 p) {
    const u64 C_ISQ2 = pk2(0.70710678118654752440f, 0.70710678118654752440f);
    u64 u  = fmul2(p, C_ISQ2);
    u64 u2 = fmul2(u, u);
    float u2a, u2b; upk2(u2, u2a, u2b);
    if (fmaxf(u2a, u2b) < 0.49f) {
        const u64 C_A = pk2(1.0f / 216.0f, 1.0f / 216.0f);
        const u64 C_B = pk2(-1.0f / 42.0f, -1.0f / 42.0f);
        const u64 C_C = pk2(0.1f, 0.1f);
        const u64 C_D = pk2(-1.0f / 3.0f, -1.0f / 3.0f);
        const u64 C_1 = pk2(1.0f, 1.0f);
        const u64 C_HK = pk2(0.56418958354775628695f, 0.56418958354775628695f);
        const u64 C_H  = pk2(0.5f, 0.5f);
        u64 t = ffma2(u2, C_A, C_B);
        t = ffma2(t, u2, C_C);
        t = ffma2(t, u2, C_D);
        t = ffma2(t, u2, C_1);
        u64 e = fmul2(u, t);                  // u * poly
        u64 h = ffma2(e, C_HK, C_H);          // 0.5 + 0.5*erf
        return fmul2(p, h);
    } else {
        float pa, pb; upk2(p, pa, pb);
        float ga = pa * (0.5f + 0.5f * erff(pa * 0.70710678118654752440f));
        float gb = pb * (0.5f + 0.5f * erff(pb * 0.70710678118654752440f));
        return pk2(ga, gb);
    }
}

// ---------------------------------------------------------------------------
// Stage A: partial GEMM  h_part[c][b][o] = sum_{e in chunk c} token[b][e]*wdec[e][o]
// grid (NDEC/OT, KC, 2): each block handles BH=32 batches packed as 16 f32x2
// pairs in smem. Per e: 16 LDS.64 + 1 LDG + 16 FFMA2. acc = 32 regs, no spill.
// ---------------------------------------------------------------------------
__global__ void __launch_bounds__(OT) stageA(const float* __restrict__ token,
                                             const float* __restrict__ wdec, int B) {
    __shared__ u64 tok2[BH / 2][KCHUNK];
    const int o  = blockIdx.x * OT + threadIdx.x;
    const int k0 = blockIdx.y * KCHUNK;
    const int b0 = blockIdx.z * BH;

    for (int i = threadIdx.x; i < (BH / 2) * KCHUNK; i += OT) {
        int p = i / KCHUNK, e = i % KCHUNK;
        int bb = b0 + 2 * p;
        float v0 = (bb     < B) ? token[(size_t)bb * EMB + k0 + e]       : 0.0f;
        float v1 = (bb + 1 < B) ? token[(size_t)(bb + 1) * EMB + k0 + e] : 0.0f;
        tok2[p][e] = pk2(v0, v1);
    }
    __syncthreads();

    u64 acc[BH / 2];
#pragma unroll
    for (int p = 0; p < BH / 2; p++) acc[p] = 0ULL;

    const float* wp = wdec + (size_t)k0 * NDEC + o;
#pragma unroll 4
    for (int e = 0; e < KCHUNK; e++) {
        float wv = wp[(size_t)e * NDEC];
        u64 wv2 = pk2(wv, wv);
#pragma unroll
        for (int p = 0; p < BH / 2; p++) acc[p] = ffma2(tok2[p][e], wv2, acc[p]);
    }

    float* dst = g_hpart[blockIdx.y];
#pragma unroll
    for (int p = 0; p < BH / 2; p++) {
        float a, bval; upk2(acc[p], a, bval);
        dst[(size_t)(b0 + 2 * p)     * NDEC + o] = a;
        dst[(size_t)(b0 + 2 * p + 1) * NDEC + o] = bval;
    }
}

// ---------------------------------------------------------------------------
// Stage B: reduce K-split partials + bias, then fold irfft scales + fc1 weight
// into per-batch trig coefficients:
//   Coef[b][0][j]    = (1/L)  * sum_w re[b,w,0] * w1[w,j]        (DC; Im ignored)
//   Coef[b][k][j]    = (2/L)  * sum_w re[b,w,k] * w1[w,j]  k=1..15   (cos)
//   Coef[b][15+k][j] = (-2/L) * sum_w im[b,w,k] * w1[w,j]  k=1..15   (sin)
// h layout per row: idx = w*32 + k*2 + {0=re,1=im}
// ---------------------------------------------------------------------------
__global__ void stageB(const float* __restrict__ w1,
                       const float* __restrict__ bdec, float invL) {
    __shared__ float hs[NDEC];
    __shared__ float w1s[WIDTH * NH];
    const int b = blockIdx.x;
    const int j = threadIdx.x;  // 128 threads

    for (int i = j; i < NDEC; i += NH) {
        float s = bdec[i];
#pragma unroll
        for (int c = 0; c < KC; c++) s += g_hpart[c][b * NDEC + i];
        hs[i] = s;
    }
    for (int i = j; i < WIDTH * NH; i += NH) w1s[i] = w1[i];
    __syncthreads();

    {   // DC term
        float a = 0.0f;
#pragma unroll
        for (int w = 0; w < WIDTH; w++) a += hs[w * 32] * w1s[w * NH + j];
        g_coef[(b * NKK + 0) * NH + j] = a * invL;
    }
#pragma unroll
    for (int k = 1; k < MODES; k++) {
        float ac = 0.0f, as = 0.0f;
#pragma unroll
        for (int w = 0; w < WIDTH; w++) {
            float wv = w1s[w * NH + j];
            ac += hs[w * 32 + k * 2]     * wv;
            as += hs[w * 32 + k * 2 + 1] * wv;
        }
        g_coef[(b * NKK + k)      * NH + j] = ac * (2.0f * invL);
        g_coef[(b * NKK + 15 + k) * NH + j] = as * (-2.0f * invL);
    }
}

// ---------------------------------------------------------------------------
// Stage C: grid (L/2/TT + 1, B), 128 threads. Each WARP owns TW=16 t values in
// [0, L/2] and, via the mirror identity cos(wm(L-t))=cos(wmt),
// sin(wm(L-t))=-sin(wmt), emits TWO outputs per t: pre(t)=a+s, pre(L-t)=a-s.
// 4 j per thread, packed f32x2. Coef slab staged in smem (once per block).
// ---------------------------------------------------------------------------
__global__ void __launch_bounds__(NH) stageC(
        const float* __restrict__ b1, const float* __restrict__ w2,
        const float* __restrict__ b2, float* __restrict__ out,
        float omega, int TL, int L, int lmask) {
    __shared__ ulonglong2 tab[4 * TW * NM];   // [warp][tl][m] = {(c,c),(s,s)}
    __shared__ float cfs[NKK * NH];           // coef slab for this batch
    __shared__ float b1s[NH], w2s[NH];

    const int b    = blockIdx.y;
    const int j    = threadIdx.x;
    const int warp = j >> 5, lane = j & 31;
    const int tw0  = blockIdx.x * TT + warp * TW;   // this warp's first t
    const int halfL = L >> 1;

    // stage coef slab + b1 + w2 into smem
    {
        const float4* src = (const float4*)(g_coef + (size_t)b * NKK * NH);
        float4* dstv = (float4*)cfs;
        for (int i = j; i < (NKK * NH) / 4; i += NH) dstv[i] = src[i];
        b1s[j] = b1[j];
        w2s[j] = w2[j];
    }

    // fill warp-private trig table (exact integer angle reduction + __sincosf)
    ulonglong2* mytab = tab + warp * TW * NM;
    for (int i = lane; i < TW * NM; i += 32) {
        int tl = i / NM, m = i - tl * NM;
        int v  = (m + 1) * (tw0 + tl);
        int r  = (lmask >= 0) ? (v & lmask) : (v % L);
        float ang = omega * (float)r;
        float s, c;
        __sincosf(ang, &s, &c);
        mytab[i] = make_ulonglong2(pk2(c, c), pk2(s, s));
    }
    __syncthreads();

    // per-thread coefficients: j0..j3 = lane, lane+32, lane+64, lane+96
    const int j0 = lane, j1 = lane + 32, j2 = lane + 64, j3 = lane + 96;
    const u64 c01 = pk2(cfs[j0] + b1s[j0], cfs[j1] + b1s[j1]);
    const u64 c23 = pk2(cfs[j2] + b1s[j2], cfs[j3] + b1s[j3]);
    u64 cc01[NM], cc23[NM], sv01[NM], sv23[NM];
#pragma unroll
    for (int m = 0; m < NM; m++) {
        const float* p = cfs + (1 + m) * NH;
        cc01[m] = pk2(p[j0], p[j1]);
        cc23[m] = pk2(p[j2], p[j3]);
        const float* q = cfs + (16 + m) * NH;
        sv01[m] = pk2(q[j0], q[j1]);
        sv23[m] = pk2(q[j2], q[j3]);
    }
    const u64 w2_01 = pk2(w2s[j0], w2s[j1]);
    const u64 w2_23 = pk2(w2s[j2], w2s[j3]);
    const float b2v = b2[0];

#pragma unroll 2
    for (int tl = 0; tl < TW; tl++) {
        u64 a01 = c01, a23 = c23, s01 = 0ULL, s23 = 0ULL;
        const ulonglong2* tp = mytab + tl * NM;
#pragma unroll
        for (int m = 0; m < NM; m++) {
            ulonglong2 q = tp[m];
            a01 = ffma2(cc01[m], q.x, a01);
            a23 = ffma2(cc23[m], q.x, a23);
            s01 = ffma2(sv01[m], q.y, s01);
            s23 = ffma2(sv23[m], q.y, s23);
        }
        // plus branch -> output t ; minus branch -> output L - t
        u64 gp01 = gelu2(fadd2(a01, s01));
        u64 gp23 = gelu2(fadd2(a23, s23));
        u64 gm01 = gelu2(fsub2(a01, s01));
        u64 gm23 = gelu2(fsub2(a23, s23));

        u64 accp = ffma2(gp01, w2_01, fmul2(gp23, w2_23));
        u64 accm = ffma2(gm01, w2_01, fmul2(gm23, w2_23));
        float pa, pb, ma, mb;
        upk2(accp, pa, pb);
        upk2(accm, ma, mb);
        float rp = pa + pb, rm = ma + mb;
#pragma unroll
        for (int off = 16; off; off >>= 1) {
            rp += __shfl_xor_sync(0xffffffffu, rp, off);
            rm += __shfl_xor_sync(0xffffffffu, rm, off);
        }

        int t   = tw0 + tl;
        int tmi = L - t;
        if (lane == 0) {
            if (t <= halfL && t < TL)
                out[(size_t)b * TL + t] = rp + b2v;
            if (tmi > halfL && tmi < TL)
                out[(size_t)b * TL + tmi] = rm + b2v;
        }
    }
}

// ---------------------------------------------------------------------------
extern "C" void kernel_launch(void* const* d_in, const int* in_sizes, int n_in,
                              void* d_out, int out_size) {
    // inputs: token, [x_len], w_dec, b_dec, w1, b1, w2, b2
    const int off = (n_in == 8) ? 1 : 0;
    const float* token = (const float*)d_in[0];
    const float* wdec  = (const float*)d_in[1 + off];
    const float* bdec  = (const float*)d_in[2 + off];
    const float* w1    = (const float*)d_in[3 + off];
    const float* b1    = (const float*)d_in[4 + off];
    const float* w2    = (const float*)d_in[5 + off];
    const float* b2    = (const float*)d_in[6 + off];
    float* out = (float*)d_out;

    int B  = in_sizes[0] / EMB;         // 64
    int TL = out_size / B;              // L - 2 = 8190
    int L  = TL + 2;                    // 8192
    float invL  = 1.0f / (float)L;
    float omega = (float)(2.0 * 3.14159265358979323846 / (double)L);
    int lmask = ((L & (L - 1)) == 0) ? (L - 1) : -1;

    stageA<<<dim3(NDEC / OT, KC, 2), OT>>>(token, wdec, B);

    stageB<<<B, NH>>>(w1, bdec, invL);

    int gx = (L / 2) / TT + 1;          // covers t in [0, L/2] (+ guard tile)
    stageC<<<dim3(gx, B), NH>>>(b1, w2, b2, out, omega, TL, L, lmask);
}

// round 7
// speedup vs baseline: 1.4297x; 1.4297x over previous
#include <cuda_runtime.h>
#include <math.h>

#define EMB    1024
#define NDEC   2048     // WIDTH*MODES*2
#define WIDTH  64
#define MODES  16
#define NH     128      // fc1 hidden
#define MAXB   64
#define KC     16       // K-split chunks in stage A
#define KCHUNK 64       // EMB / KC
#define OT     256      // output-column tile in stage A
#define BH     32       // batches per stage-A block (2-way batch split)
#define NKK    31       // 1 DC + 15 cos + 15 sin
#define TT     64       // t-tile per block in stage C
#define TW     16       // t per warp in stage C
#define NM     15       // MODES-1

typedef unsigned long long u64;

// Scratch (static device globals; no allocation)
__device__ float g_hpart[KC][MAXB * NDEC];   // 8 MB
__device__ float g_coef[MAXB * NKK * NH];    // ~1 MB

// ---- packed f32x2 helpers (sm_100+) --------------------------------------
__device__ __forceinline__ u64 pk2(float lo, float hi) {
    u64 r; asm("mov.b64 %0, {%1, %2};" : "=l"(r) : "f"(lo), "f"(hi)); return r;
}
__device__ __forceinline__ void upk2(u64 v, float& lo, float& hi) {
    asm("mov.b64 {%0, %1}, %2;" : "=f"(lo), "=f"(hi) : "l"(v));
}
__device__ __forceinline__ u64 ffma2(u64 a, u64 b, u64 c) {
    u64 d; asm("fma.rn.f32x2 %0, %1, %2, %3;" : "=l"(d) : "l"(a), "l"(b), "l"(c)); return d;
}
__device__ __forceinline__ u64 fadd2(u64 a, u64 b) {
    u64 d; asm("add.rn.f32x2 %0, %1, %2;" : "=l"(d) : "l"(a), "l"(b)); return d;
}
__device__ __forceinline__ u64 fsub2(u64 a, u64 b) {
    u64 d; asm("sub.rn.f32x2 %0, %1, %2;" : "=l"(d) : "l"(a), "l"(b)); return d;
}

// exact-enough gelu: Taylor erf for small args (always the real case here;
// |pre| ~ 1e-2), erff fallback otherwise.
__device__ __forceinline__ float gelu_f(float x) {
    float u  = x * 0.70710678118654752440f;
    float u2 = u * u;
    float e;
    if (u2 < 0.49f) {
        float t = fmaf(u2, 1.0f / 216.0f, -1.0f / 42.0f);
        t = fmaf(t, u2, 0.1f);
        t = fmaf(t, u2, -1.0f / 3.0f);
        t = fmaf(t, u2, 1.0f);
        e = (1.12837916709551257390f * u) * t;
    } else {
        e = erff(u);
    }
    return x * fmaf(0.5f, e, 0.5f);
}

// ---------------------------------------------------------------------------
// Stage A: partial GEMM  h_part[c][b][o] = sum_{e in chunk c} token[b][e]*wdec[e][o]
// grid (NDEC/OT, KC, 2): each block handles BH=32 batches packed as 16 f32x2
// pairs in smem. Per e: 16 LDS.64 (broadcast) + 1 LDG + 16 FFMA2.
// ---------------------------------------------------------------------------
__global__ void __launch_bounds__(OT) stageA(const float* __restrict__ token,
                                             const float* __restrict__ wdec, int B) {
    __shared__ u64 tok2[BH / 2][KCHUNK];
    const int o  = blockIdx.x * OT + threadIdx.x;
    const int k0 = blockIdx.y * KCHUNK;
    const int b0 = blockIdx.z * BH;

    for (int i = threadIdx.x; i < (BH / 2) * KCHUNK; i += OT) {
        int p = i / KCHUNK, e = i % KCHUNK;
        int bb = b0 + 2 * p;
        float v0 = (bb     < B) ? token[(size_t)bb * EMB + k0 + e]       : 0.0f;
        float v1 = (bb + 1 < B) ? token[(size_t)(bb + 1) * EMB + k0 + e] : 0.0f;
        tok2[p][e] = pk2(v0, v1);
    }
    __syncthreads();

    u64 acc[BH / 2];
#pragma unroll
    for (int p = 0; p < BH / 2; p++) acc[p] = 0ULL;

    const float* wp = wdec + (size_t)k0 * NDEC + o;
#pragma unroll 4
    for (int e = 0; e < KCHUNK; e++) {
        float wv = wp[(size_t)e * NDEC];
        u64 wv2 = pk2(wv, wv);
#pragma unroll
        for (int p = 0; p < BH / 2; p++) acc[p] = ffma2(tok2[p][e], wv2, acc[p]);
    }

    float* dst = g_hpart[blockIdx.y];
#pragma unroll
    for (int p = 0; p < BH / 2; p++) {
        float a, bval; upk2(acc[p], a, bval);
        dst[(size_t)(b0 + 2 * p)     * NDEC + o] = a;
        dst[(size_t)(b0 + 2 * p + 1) * NDEC + o] = bval;
    }
}

// ---------------------------------------------------------------------------
// Stage B: reduce K-split partials + bias, then fold irfft scales + fc1 weight
// into per-batch trig coefficients (h row layout: idx = w*32 + k*2 + {re,im}):
//   Coef[b][0][j]    = (1/L)  * sum_w re[b,w,0] * w1[w,j]        (DC; Im ignored)
//   Coef[b][k][j]    = (2/L)  * sum_w re[b,w,k] * w1[w,j]  k=1..15   (cos)
//   Coef[b][15+k][j] = (-2/L) * sum_w im[b,w,k] * w1[w,j]  k=1..15   (sin)
// ---------------------------------------------------------------------------
__global__ void stageB(const float* __restrict__ w1,
                       const float* __restrict__ bdec, float invL) {
    __shared__ float hs[NDEC];
    __shared__ float w1s[WIDTH * NH];
    const int b = blockIdx.x;
    const int j = threadIdx.x;  // 128 threads

    for (int i = j; i < NDEC; i += NH) {
        float s = bdec[i];
#pragma unroll
        for (int c = 0; c < KC; c++) s += g_hpart[c][b * NDEC + i];
        hs[i] = s;
    }
    for (int i = j; i < WIDTH * NH; i += NH) w1s[i] = w1[i];
    __syncthreads();

    {   // DC term
        float a = 0.0f;
#pragma unroll
        for (int w = 0; w < WIDTH; w++) a += hs[w * 32] * w1s[w * NH + j];
        g_coef[(b * NKK + 0) * NH + j] = a * invL;
    }
#pragma unroll
    for (int k = 1; k < MODES; k++) {
        float ac = 0.0f, as = 0.0f;
#pragma unroll
        for (int w = 0; w < WIDTH; w++) {
            float wv = w1s[w * NH + j];
            ac += hs[w * 32 + k * 2]     * wv;
            as += hs[w * 32 + k * 2 + 1] * wv;
        }
        g_coef[(b * NKK + k)      * NH + j] = ac * (2.0f * invL);
        g_coef[(b * NKK + 15 + k) * NH + j] = as * (-2.0f * invL);
    }
}

// ---------------------------------------------------------------------------
// Stage C: grid (L/2/TT + 1, B), 128 threads, pinned 3 blocks/SM. Each WARP
// owns TW=16 t in [0, L/2]; mirror identity (cos even, sin odd about L/2)
// gives 2 outputs per iteration: pre(t)=a+s, pre(L-t)=a-s.
// Epilogue: scalar gelus computed sequentially with reused temporaries (low
// register pressure), then the two 5-step SHFL chains interleaved so their
// 26-cycle latencies overlap.
// ---------------------------------------------------------------------------
__global__ void __launch_bounds__(NH, 3) stageC(
        const float* __restrict__ b1, const float* __restrict__ w2,
        const float* __restrict__ b2, float* __restrict__ out,
        float omega, int TL, int L, int lmask) {
    __shared__ ulonglong2 tab[4 * TW * NM];   // [warp][tl][m] = {(c,c),(s,s)}
    __shared__ float cfs[NKK * NH];           // coef slab for this batch
    __shared__ float b1s[NH], w2s[NH];

    const int b    = blockIdx.y;
    const int j    = threadIdx.x;
    const int warp = j >> 5, lane = j & 31;
    const int tw0  = blockIdx.x * TT + warp * TW;   // this warp's first t
    const int halfL = L >> 1;

    // stage coef slab + b1 + w2 into smem
    {
        const float4* src = (const float4*)(g_coef + (size_t)b * NKK * NH);
        float4* dstv = (float4*)cfs;
        for (int i = j; i < (NKK * NH) / 4; i += NH) dstv[i] = src[i];
        b1s[j] = b1[j];
        w2s[j] = w2[j];
    }

    // fill warp-private trig table (exact integer angle reduction + __sincosf)
    ulonglong2* mytab = tab + warp * TW * NM;
    for (int i = lane; i < TW * NM; i += 32) {
        int tl = i / NM, m = i - tl * NM;
        int v  = (m + 1) * (tw0 + tl);
        int r  = (lmask >= 0) ? (v & lmask) : (v % L);
        float ang = omega * (float)r;
        float s, c;
        __sincosf(ang, &s, &c);
        mytab[i] = make_ulonglong2(pk2(c, c), pk2(s, s));
    }
    __syncthreads();

    // per-thread coefficients: j0..j3 = lane, lane+32, lane+64, lane+96
    const int j0 = lane, j1 = lane + 32, j2 = lane + 64, j3 = lane + 96;
    const u64 c01 = pk2(cfs[j0] + b1s[j0], cfs[j1] + b1s[j1]);
    const u64 c23 = pk2(cfs[j2] + b1s[j2], cfs[j3] + b1s[j3]);
    u64 cc01[NM], cc23[NM], sv01[NM], sv23[NM];
#pragma unroll
    for (int m = 0; m < NM; m++) {
        const float* p = cfs + (1 + m) * NH;
        cc01[m] = pk2(p[j0], p[j1]);
        cc23[m] = pk2(p[j2], p[j3]);
        const float* q = cfs + (16 + m) * NH;
        sv01[m] = pk2(q[j0], q[j1]);
        sv23[m] = pk2(q[j2], q[j3]);
    }
    const float w20 = w2s[j0], w21 = w2s[j1], w22 = w2s[j2], w23 = w2s[j3];
    const float b2v = b2[0];

    for (int tl = 0; tl < TW; tl++) {
        u64 a01 = c01, a23 = c23, s01 = 0ULL, s23 = 0ULL;
        const ulonglong2* tp = mytab + tl * NM;
#pragma unroll
        for (int m = 0; m < NM; m++) {
            ulonglong2 q = tp[m];
            a01 = ffma2(cc01[m], q.x, a01);
            a23 = ffma2(cc23[m], q.x, a23);
            s01 = ffma2(sv01[m], q.y, s01);
            s23 = ffma2(sv23[m], q.y, s23);
        }

        // plus branch (output t): sequential scalar gelus, reused temporaries
        float rp;
        {
            float x0, x1, x2, x3;
            upk2(fadd2(a01, s01), x0, x1);
            upk2(fadd2(a23, s23), x2, x3);
            rp = gelu_f(x0) * w20;
            rp = fmaf(gelu_f(x1), w21, rp);
            rp = fmaf(gelu_f(x2), w22, rp);
            rp = fmaf(gelu_f(x3), w23, rp);
        }
        // minus branch (output L - t): same temporaries reused
        float rm;
        {
            float x0, x1, x2, x3;
            upk2(fsub2(a01, s01), x0, x1);
            upk2(fsub2(a23, s23), x2, x3);
            rm = gelu_f(x0) * w20;
            rm = fmaf(gelu_f(x1), w21, rm);
            rm = fmaf(gelu_f(x2), w22, rm);
            rm = fmaf(gelu_f(x3), w23, rm);
        }
        // interleaved butterfly reductions (independent latency chains)
#pragma unroll
        for (int off = 16; off; off >>= 1) {
            rp += __shfl_xor_sync(0xffffffffu, rp, off);
            rm += __shfl_xor_sync(0xffffffffu, rm, off);
        }

        int t   = tw0 + tl;
        int tmi = L - t;
        if (lane == 0) {
            if (t <= halfL && t < TL)
                out[(size_t)b * TL + t] = rp + b2v;
            if (tmi > halfL && tmi < TL)
                out[(size_t)b * TL + tmi] = rm + b2v;
        }
    }
}

// ---------------------------------------------------------------------------
extern "C" void kernel_launch(void* const* d_in, const int* in_sizes, int n_in,
                              void* d_out, int out_size) {
    // inputs: token, [x_len], w_dec, b_dec, w1, b1, w2, b2
    const int off = (n_in == 8) ? 1 : 0;
    const float* token = (const float*)d_in[0];
    const float* wdec  = (const float*)d_in[1 + off];
    const float* bdec  = (const float*)d_in[2 + off];
    const float* w1    = (const float*)d_in[3 + off];
    const float* b1    = (const float*)d_in[4 + off];
    const float* w2    = (const float*)d_in[5 + off];
    const float* b2    = (const float*)d_in[6 + off];
    float* out = (float*)d_out;

    int B  = in_sizes[0] / EMB;         // 64
    int TL = out_size / B;              // L - 2 = 8190
    int L  = TL + 2;                    // 8192
    float invL  = 1.0f / (float)L;
    float omega = (float)(2.0 * 3.14159265358979323846 / (double)L);
    int lmask = ((L & (L - 1)) == 0) ? (L - 1) : -1;

    stageA<<<dim3(NDEC / OT, KC, 2), OT>>>(token, wdec, B);

    stageB<<<B, NH>>>(w1, bdec, invL);

    int gx = (L / 2) / TT + 1;          // covers t in [0, L/2] (+ guard tile)
    stageC<<<dim3(gx, B), NH>>>(b1, w2, b2, out, omega, TL, L, lmask);
}

// round 8
// speedup vs baseline: 2.0259x; 1.4170x over previous
#include <cuda_runtime.h>
#include <math.h>

#define EMB    1024
#define NDEC   2048     // WIDTH*MODES*2
#define WIDTH  64
#define MODES  16
#define NH     128      // fc1 hidden
#define MAXB   64
#define KC     16       // K-split chunks in stage A
#define KCHUNK 64       // EMB / KC
#define OT     256      // output-column tile in stage A
#define BH     32       // batches per stage-A block (2-way batch split)
#define NKK    31       // 1 DC + 15 cos + 15 sin
#define TT     64       // t-tile per block in stage C
#define TW     16       // t per warp in stage C
#define NM     15       // MODES-1

typedef unsigned long long u64;

// Scratch (static device globals; no allocation)
__device__ float g_hpart[KC][MAXB * NDEC];   // 8 MB
__device__ float g_coef[MAXB * NKK * NH];    // ~1 MB

// ---- packed f32x2 helpers (sm_100+) --------------------------------------
__device__ __forceinline__ u64 pk2(float lo, float hi) {
    u64 r; asm("mov.b64 %0, {%1, %2};" : "=l"(r) : "f"(lo), "f"(hi)); return r;
}
__device__ __forceinline__ void upk2(u64 v, float& lo, float& hi) {
    asm("mov.b64 {%0, %1}, %2;" : "=f"(lo), "=f"(hi) : "l"(v));
}
__device__ __forceinline__ u64 ffma2(u64 a, u64 b, u64 c) {
    u64 d; asm("fma.rn.f32x2 %0, %1, %2, %3;" : "=l"(d) : "l"(a), "l"(b), "l"(c)); return d;
}
__device__ __forceinline__ u64 fadd2(u64 a, u64 b) {
    u64 d; asm("add.rn.f32x2 %0, %1, %2;" : "=l"(d) : "l"(a), "l"(b)); return d;
}
__device__ __forceinline__ u64 fsub2(u64 a, u64 b) {
    u64 d; asm("sub.rn.f32x2 %0, %1, %2;" : "=l"(d) : "l"(a), "l"(b)); return d;
}
__device__ __forceinline__ u64 fmul2(u64 a, u64 b) {
    u64 d; asm("mul.rn.f32x2 %0, %1, %2;" : "=l"(d) : "l"(a), "l"(b)); return d;
}

// packed exact-enough gelu: Taylor erf for small args (always the real case
// here; |pre| ~ 1e-2), scalar erff fallback otherwise.
__device__ __forceinline__ u64 gelu2(u64 p) {
    const u64 C_ISQ2 = pk2(0.70710678118654752440f, 0.70710678118654752440f);
    u64 u  = fmul2(p, C_ISQ2);
    u64 u2 = fmul2(u, u);
    float u2a, u2b; upk2(u2, u2a, u2b);
    if (fmaxf(u2a, u2b) < 0.49f) {
        const u64 C_A = pk2(1.0f / 216.0f, 1.0f / 216.0f);
        const u64 C_B = pk2(-1.0f / 42.0f, -1.0f / 42.0f);
        const u64 C_C = pk2(0.1f, 0.1f);
        const u64 C_D = pk2(-1.0f / 3.0f, -1.0f / 3.0f);
        const u64 C_1 = pk2(1.0f, 1.0f);
        const u64 C_HK = pk2(0.56418958354775628695f, 0.56418958354775628695f);
        const u64 C_H  = pk2(0.5f, 0.5f);
        u64 t = ffma2(u2, C_A, C_B);
        t = ffma2(t, u2, C_C);
        t = ffma2(t, u2, C_D);
        t = ffma2(t, u2, C_1);
        u64 e = fmul2(u, t);                  // u * poly
        u64 h = ffma2(e, C_HK, C_H);          // 0.5 + 0.5*erf
        return fmul2(p, h);
    } else {
        float pa, pb; upk2(p, pa, pb);
        float ga = pa * (0.5f + 0.5f * erff(pa * 0.70710678118654752440f));
        float gb = pb * (0.5f + 0.5f * erff(pb * 0.70710678118654752440f));
        return pk2(ga, gb);
    }
}

// ---------------------------------------------------------------------------
// Stage A: partial GEMM  h_part[c][b][o] = sum_{e in chunk c} token[b][e]*wdec[e][o]
// grid (NDEC/OT, KC, 2): each block handles BH=32 batches packed as 16 f32x2
// pairs in smem. Per e: 16 LDS.64 (broadcast) + 1 LDG + 16 FFMA2.
// ---------------------------------------------------------------------------
__global__ void __launch_bounds__(OT) stageA(const float* __restrict__ token,
                                             const float* __restrict__ wdec, int B) {
    __shared__ u64 tok2[BH / 2][KCHUNK];
    const int o  = blockIdx.x * OT + threadIdx.x;
    const int k0 = blockIdx.y * KCHUNK;
    const int b0 = blockIdx.z * BH;

    for (int i = threadIdx.x; i < (BH / 2) * KCHUNK; i += OT) {
        int p = i / KCHUNK, e = i % KCHUNK;
        int bb = b0 + 2 * p;
        float v0 = (bb     < B) ? token[(size_t)bb * EMB + k0 + e]       : 0.0f;
        float v1 = (bb + 1 < B) ? token[(size_t)(bb + 1) * EMB + k0 + e] : 0.0f;
        tok2[p][e] = pk2(v0, v1);
    }
    __syncthreads();

    u64 acc[BH / 2];
#pragma unroll
    for (int p = 0; p < BH / 2; p++) acc[p] = 0ULL;

    const float* wp = wdec + (size_t)k0 * NDEC + o;
#pragma unroll 8
    for (int e = 0; e < KCHUNK; e++) {
        float wv = wp[(size_t)e * NDEC];
        u64 wv2 = pk2(wv, wv);
#pragma unroll
        for (int p = 0; p < BH / 2; p++) acc[p] = ffma2(tok2[p][e], wv2, acc[p]);
    }

    float* dst = g_hpart[blockIdx.y];
#pragma unroll
    for (int p = 0; p < BH / 2; p++) {
        float a, bval; upk2(acc[p], a, bval);
        dst[(size_t)(b0 + 2 * p)     * NDEC + o] = a;
        dst[(size_t)(b0 + 2 * p + 1) * NDEC + o] = bval;
    }
}

// ---------------------------------------------------------------------------
// Stage B: reduce K-split partials + bias, then fold irfft scales + fc1 weight
// into per-batch trig coefficients (h row layout: idx = w*32 + k*2 + {re,im}):
//   Coef[b][0][j]    = (1/L)  * sum_w re[b,w,0] * w1[w,j]        (DC; Im ignored)
//   Coef[b][k][j]    = (2/L)  * sum_w re[b,w,k] * w1[w,j]  k=1..15   (cos)
//   Coef[b][15+k][j] = (-2/L) * sum_w im[b,w,k] * w1[w,j]  k=1..15   (sin)
// ---------------------------------------------------------------------------
__global__ void stageB(const float* __restrict__ w1,
                       const float* __restrict__ bdec, float invL) {
    __shared__ float hs[NDEC];
    __shared__ float w1s[WIDTH * NH];
    const int b = blockIdx.x;
    const int j = threadIdx.x;  // 128 threads

    for (int i = j; i < NDEC; i += NH) {
        float s = bdec[i];
#pragma unroll
        for (int c = 0; c < KC; c++) s += g_hpart[c][b * NDEC + i];
        hs[i] = s;
    }
    for (int i = j; i < WIDTH * NH; i += NH) w1s[i] = w1[i];
    __syncthreads();

    {   // DC term
        float a = 0.0f;
#pragma unroll
        for (int w = 0; w < WIDTH; w++) a += hs[w * 32] * w1s[w * NH + j];
        g_coef[(b * NKK + 0) * NH + j] = a * invL;
    }
#pragma unroll
    for (int k = 1; k < MODES; k++) {
        float ac = 0.0f, as = 0.0f;
#pragma unroll
        for (int w = 0; w < WIDTH; w++) {
            float wv = w1s[w * NH + j];
            ac += hs[w * 32 + k * 2]     * wv;
            as += hs[w * 32 + k * 2 + 1] * wv;
        }
        g_coef[(b * NKK + k)      * NH + j] = ac * (2.0f * invL);
        g_coef[(b * NKK + 15 + k) * NH + j] = as * (-2.0f * invL);
    }
}

// ---------------------------------------------------------------------------
// Stage C: quarter-wave. grid (L/4/TT + 1, B), 128 threads, 3 blocks/SM.
// Each warp owns TW=16 t in [0, L/4]. Accumulators split by MODE PARITY:
//   Ae/Ao = even/odd-mode cos sums, Se/So = even/odd-mode sin sums.
// One m-loop yields FOUR outputs:
//   pre(t)     = base + (Ae+Ao) + (Se+So)    pre(L-t)   = base + (Ae+Ao) - (Se+So)
//   pre(L/2-t) = base + (Ae-Ao) - (Se-So)    pre(L/2+t) = base + (Ae-Ao) + (Se-So)
// 4 j per thread (packed f32x2), packed gelu2, 4 interleaved SHFL butterflies.
// Seam duplicates (t=0, t=L/4) are same-thread sequential stores: deterministic.
// ---------------------------------------------------------------------------
__global__ void __launch_bounds__(NH, 3) stageC(
        const float* __restrict__ b1, const float* __restrict__ w2,
        const float* __restrict__ b2, float* __restrict__ out,
        float omega, int TL, int L, int lmask) {
    __shared__ ulonglong2 tab[4 * TW * NM];   // [warp][tl][m] = {(c,c),(s,s)}
    __shared__ float cfs[NKK * NH];           // coef slab for this batch
    __shared__ float b1s[NH], w2s[NH];

    const int b    = blockIdx.y;
    const int j    = threadIdx.x;
    const int warp = j >> 5, lane = j & 31;
    const int tw0  = blockIdx.x * TT + warp * TW;   // this warp's first t
    const int quarterL = L >> 2;
    const int halfL    = L >> 1;

    // stage coef slab + b1 + w2 into smem
    {
        const float4* src = (const float4*)(g_coef + (size_t)b * NKK * NH);
        float4* dstv = (float4*)cfs;
        for (int i = j; i < (NKK * NH) / 4; i += NH) dstv[i] = src[i];
        b1s[j] = b1[j];
        w2s[j] = w2[j];
    }

    // fill warp-private trig table (exact integer angle reduction + __sincosf)
    ulonglong2* mytab = tab + warp * TW * NM;
    for (int i = lane; i < TW * NM; i += 32) {
        int tl = i / NM, m = i - tl * NM;
        int v  = (m + 1) * (tw0 + tl);
        int r  = (lmask >= 0) ? (v & lmask) : (v % L);
        float ang = omega * (float)r;
        float s, c;
        __sincosf(ang, &s, &c);
        mytab[i] = make_ulonglong2(pk2(c, c), pk2(s, s));
    }
    __syncthreads();

    // per-thread coefficients: j0..j3 = lane, lane+32, lane+64, lane+96
    const int j0 = lane, j1 = lane + 32, j2 = lane + 64, j3 = lane + 96;
    const u64 base01 = pk2(cfs[j0] + b1s[j0], cfs[j1] + b1s[j1]);
    const u64 base23 = pk2(cfs[j2] + b1s[j2], cfs[j3] + b1s[j3]);
    u64 cc01[NM], cc23[NM], sv01[NM], sv23[NM];
#pragma unroll
    for (int m = 0; m < NM; m++) {
        const float* p = cfs + (1 + m) * NH;
        cc01[m] = pk2(p[j0], p[j1]);
        cc23[m] = pk2(p[j2], p[j3]);
        const float* q = cfs + (16 + m) * NH;
        sv01[m] = pk2(q[j0], q[j1]);
        sv23[m] = pk2(q[j2], q[j3]);
    }
    const u64 w2_01 = pk2(w2s[j0], w2s[j1]);
    const u64 w2_23 = pk2(w2s[j2], w2s[j3]);
    const float b2v = b2[0];

    for (int tl = 0; tl < TW; tl++) {
        const int t = tw0 + tl;
        if (t > quarterL) break;

        // parity-split accumulation (mode k = m+1; odd m => even mode)
        u64 ae01 = 0, ao01 = 0, se01 = 0, so01 = 0;
        u64 ae23 = 0, ao23 = 0, se23 = 0, so23 = 0;
        const ulonglong2* tp = mytab + tl * NM;
#pragma unroll
        for (int m = 0; m < NM; m++) {
            ulonglong2 q = tp[m];
            if (m & 1) {   // mode even
                ae01 = ffma2(cc01[m], q.x, ae01);
                ae23 = ffma2(cc23[m], q.x, ae23);
                se01 = ffma2(sv01[m], q.y, se01);
                se23 = ffma2(sv23[m], q.y, se23);
            } else {       // mode odd
                ao01 = ffma2(cc01[m], q.x, ao01);
                ao23 = ffma2(cc23[m], q.x, ao23);
                so01 = ffma2(sv01[m], q.y, so01);
                so23 = ffma2(sv23[m], q.y, so23);
            }
        }

        // combine into the 4 pre-activations per pack
        u64 u01 = fadd2(ae01, ao01), v01 = fsub2(ae01, ao01);
        u64 p01 = fadd2(se01, so01), q01 = fsub2(se01, so01);
        u64 u23 = fadd2(ae23, ao23), v23 = fsub2(ae23, ao23);
        u64 p23 = fadd2(se23, so23), q23 = fsub2(se23, so23);
        u64 bu01 = fadd2(base01, u01), bv01 = fadd2(base01, v01);
        u64 bu23 = fadd2(base23, u23), bv23 = fadd2(base23, v23);

        float r0, r1, r2, r3;
        {   // output t : bu + p
            u64 g01 = gelu2(fadd2(bu01, p01));
            u64 g23 = gelu2(fadd2(bu23, p23));
            u64 acc = ffma2(g01, w2_01, fmul2(g23, w2_23));
            float xa, xb; upk2(acc, xa, xb); r0 = xa + xb;
        }
        {   // output L - t : bu - p
            u64 g01 = gelu2(fsub2(bu01, p01));
            u64 g23 = gelu2(fsub2(bu23, p23));
            u64 acc = ffma2(g01, w2_01, fmul2(g23, w2_23));
            float xa, xb; upk2(acc, xa, xb); r1 = xa + xb;
        }
        {   // output L/2 - t : bv - q
            u64 g01 = gelu2(fsub2(bv01, q01));
            u64 g23 = gelu2(fsub2(bv23, q23));
            u64 acc = ffma2(g01, w2_01, fmul2(g23, w2_23));
            float xa, xb; upk2(acc, xa, xb); r2 = xa + xb;
        }
        {   // output L/2 + t : bv + q
            u64 g01 = gelu2(fadd2(bv01, q01));
            u64 g23 = gelu2(fadd2(bv23, q23));
            u64 acc = ffma2(g01, w2_01, fmul2(g23, w2_23));
            float xa, xb; upk2(acc, xa, xb); r3 = xa + xb;
        }

        // 4 interleaved butterfly reductions
#pragma unroll
        for (int off = 16; off; off >>= 1) {
            r0 += __shfl_xor_sync(0xffffffffu, r0, off);
            r1 += __shfl_xor_sync(0xffffffffu, r1, off);
            r2 += __shfl_xor_sync(0xffffffffu, r2, off);
            r3 += __shfl_xor_sync(0xffffffffu, r3, off);
        }

        if (lane == 0) {
            float* ob = out + (size_t)b * TL;
            ob[t] = r0 + b2v;                               // t <= L/4 < TL
            int i1 = L - t;
            if (i1 < TL) ob[i1] = r1 + b2v;                 // (3L/4, L)
            ob[halfL - t] = r2 + b2v;                       // [L/4, L/2]
            ob[halfL + t] = r3 + b2v;                       // [L/2, 3L/4]
        }
    }
}

// ---------------------------------------------------------------------------
extern "C" void kernel_launch(void* const* d_in, const int* in_sizes, int n_in,
                              void* d_out, int out_size) {
    // inputs: token, [x_len], w_dec, b_dec, w1, b1, w2, b2
    const int off = (n_in == 8) ? 1 : 0;
    const float* token = (const float*)d_in[0];
    const float* wdec  = (const float*)d_in[1 + off];
    const float* bdec  = (const float*)d_in[2 + off];
    const float* w1    = (const float*)d_in[3 + off];
    const float* b1    = (const float*)d_in[4 + off];
    const float* w2    = (const float*)d_in[5 + off];
    const float* b2    = (const float*)d_in[6 + off];
    float* out = (float*)d_out;

    int B  = in_sizes[0] / EMB;         // 64
    int TL = out_size / B;              // L - 2 = 8190
    int L  = TL + 2;                    // 8192
    float invL  = 1.0f / (float)L;
    float omega = (float)(2.0 * 3.14159265358979323846 / (double)L);
    int lmask = ((L & (L - 1)) == 0) ? (L - 1) : -1;

    stageA<<<dim3(NDEC / OT, KC, 2), OT>>>(token, wdec, B);

    stageB<<<B, NH>>>(w1, bdec, invL);

    int gx = (L / 4) / TT + 1;          // covers t in [0, L/4] (+ guard tile)
    stageC<<<dim3(gx, B), NH>>>(b1, w2, b2, out, omega, TL, L, lmask);
}